// round 3
// baseline (speedup 1.0000x reference)
#include <cuda_runtime.h>
#include <cuda_bf16.h>

#define BB 4096
#define SS 200
#define DD 64
#define HH 36
#define NROWS (BB * SS)

typedef unsigned long long ull;

// Scratch (__device__ globals: allocation-free rule)
__device__ float g_cterm[BB * HH];    // per-batch constant term (589 KB)
__device__ float g_part[72 * BB];     // per-block stat partials, [72][B]
__device__ float g_tot[72];
__device__ float g_scale[HH];
__device__ float g_shift[HH];

// ---- packed f32x2 helpers (Blackwell FFMA2 via PTX) ----
__device__ __forceinline__ ull pack2(float a) {
    ull r;
    asm("mov.b64 %0, {%1, %1};" : "=l"(r) : "f"(a));
    return r;
}
__device__ __forceinline__ void fma2(ull& d, ull a, ull b) {
    asm("fma.rn.f32x2 %0, %1, %2, %3;" : "=l"(d) : "l"(a), "l"(b), "l"(d));
}
__device__ __forceinline__ float2 unpack2(ull v) {
    float2 f;
    asm("mov.b64 {%0, %1}, %2;" : "=f"(f.x), "=f"(f.y) : "l"(v));
    return f;
}

// Shared-memory layout (floats), common to pass1/pass2:
//   sh_hist : [0, 13000)            200 x 65 (padded)
//   sh_W    : [13000, 15304)        64 x 36 W_eff   (16B aligned)
//   sh_c    : [15304, 15340)        36 c_term       (8B aligned)
//   sh_comb : [15340, 22740)        200 x 37 k-half combine buffer
//   pass2 extra:
//   sh_w    : [22740, 22940)        200 row weights
//   sh_misc : [22940, 23050)        sc[36] sf[36] w2[36] alpha b2
#define OFF_W    13000
#define OFF_C    15304
#define OFF_COMB 15340
#define OFF_RW   22740
#define OFF_MISC 22940
#define SMEM1_FLOATS 22740
#define SMEM2_FLOATS 23050

// =====================================================================
// prep: c_term[b][j] = b1[j] + sum_k cand[b][k]*(W1[k][j]+W1[128+k][j])
// =====================================================================
__global__ __launch_bounds__(256) void prep_kernel(
    const float* __restrict__ cand, const float* __restrict__ W1,
    const float* __restrict__ b1)
{
    __shared__ float sW[DD * HH];
    __shared__ float sc[4 * DD];
    const int tid = threadIdx.x;
    const int b0 = blockIdx.x * 4;
    for (int i = tid; i < DD * HH; i += 256) sW[i] = W1[i] + W1[128 * HH + i];
    for (int i = tid; i < 4 * DD; i += 256) sc[i] = cand[b0 * DD + i];
    __syncthreads();
    if (tid < 4 * HH) {
        int bl = tid / HH, j = tid - bl * HH;
        float s = b1[j];
        #pragma unroll 8
        for (int k = 0; k < DD; k++) s += sc[bl * DD + k] * sW[k * HH + j];
        g_cterm[(b0 + bl) * HH + j] = s;
    }
}

// =====================================================================
// Common matvec: h[200][36] = c_term + hist @ W_eff
// R=2 rows/thread (rp, rp+100), split-K2 (threads 0..99 k=0..31,
// threads 128..227 k=32..63). Final h lands in is0 threads' h0f/h1f.
// =====================================================================
__device__ __forceinline__ void block_matvec(
    const float* __restrict__ history, const float* __restrict__ cand,
    const float* __restrict__ W1, int b, float* sm,
    float* h0f, float* h1f, bool& is0, int& rp)
{
    float* sh_hist = sm;
    float* sh_W    = sm + OFF_W;
    float* sh_c    = sm + OFF_C;
    float* sh_comb = sm + OFF_COMB;
    const int tid = threadIdx.x;

    if (tid < HH) sh_c[tid] = g_cterm[b * HH + tid];
    // W_eff[k][j] = W1[64+k][j] - W1[128+k][j] + cand[k]*W1[192+k][j]
    {
        const float* cb = cand + b * DD;
        #pragma unroll
        for (int i = tid; i < DD * HH; i += 256) {
            int k = i / HH;
            sh_W[i] = W1[64 * HH + i] - W1[128 * HH + i] + __ldg(cb + k) * W1[192 * HH + i];
        }
    }
    // history tile [s][65], coalesced float4 reads
    {
        const float4* h4 = (const float4*)(history + (size_t)b * SS * DD);
        #pragma unroll 4
        for (int i4 = tid; i4 < SS * DD / 4; i4 += 256) {
            int s = i4 >> 4, kq = i4 & 15;
            float4 v = h4[i4];
            float* p = sh_hist + s * 65 + kq * 4;
            p[0] = v.x; p[1] = v.y; p[2] = v.z; p[3] = v.w;
        }
    }
    __syncthreads();

    is0 = tid < 100;
    const bool is1 = (tid >= 128 && tid < 228);
    rp = is0 ? tid : tid - 128;

    ull acc0[18], acc1[18];
    if (is0) {
        const ull* c2 = (const ull*)sh_c;
        #pragma unroll
        for (int q = 0; q < 18; q++) { acc0[q] = c2[q]; acc1[q] = c2[q]; }
    } else {
        #pragma unroll
        for (int q = 0; q < 18; q++) { acc0[q] = 0ull; acc1[q] = 0ull; }
    }

    if (is0 | is1) {
        const int k0 = is0 ? 0 : 32;
        const float* r0 = sh_hist + rp * 65 + k0;
        const float* r1 = sh_hist + (rp + 100) * 65 + k0;
        const char* Wb = (const char*)(sh_W + k0 * HH);
        #pragma unroll 2
        for (int kk = 0; kk < 32; kk++) {
            ull H0 = pack2(r0[kk]);
            ull H1 = pack2(r1[kk]);
            const ulonglong2* Wk = (const ulonglong2*)(Wb + kk * (HH * 4));
            #pragma unroll
            for (int q = 0; q < 9; q++) {
                ulonglong2 w = Wk[q];
                fma2(acc0[2 * q],     H0, w.x);
                fma2(acc0[2 * q + 1], H0, w.y);
                fma2(acc1[2 * q],     H1, w.x);
                fma2(acc1[2 * q + 1], H1, w.y);
            }
        }
    }
    // k-half combine: is1 writes partials, is0 adds
    if (is1) {
        #pragma unroll
        for (int q = 0; q < 18; q++) {
            float2 f0 = unpack2(acc0[q]);
            float2 f1 = unpack2(acc1[q]);
            sh_comb[rp * 37 + 2 * q]             = f0.x;
            sh_comb[rp * 37 + 2 * q + 1]         = f0.y;
            sh_comb[(rp + 100) * 37 + 2 * q]     = f1.x;
            sh_comb[(rp + 100) * 37 + 2 * q + 1] = f1.y;
        }
    }
    __syncthreads();
    if (is0) {
        #pragma unroll
        for (int q = 0; q < 18; q++) {
            float2 f0 = unpack2(acc0[q]);
            float2 f1 = unpack2(acc1[q]);
            h0f[2 * q]     = f0.x + sh_comb[rp * 37 + 2 * q];
            h0f[2 * q + 1] = f0.y + sh_comb[rp * 37 + 2 * q + 1];
            h1f[2 * q]     = f1.x + sh_comb[(rp + 100) * 37 + 2 * q];
            h1f[2 * q + 1] = f1.y + sh_comb[(rp + 100) * 37 + 2 * q + 1];
        }
    }
}

// =====================================================================
// Pass 1: matvec + per-block stat partials (no h store to DRAM)
// =====================================================================
__global__ __launch_bounds__(256) void pass1_kernel(
    const float* __restrict__ history, const float* __restrict__ cand,
    const float* __restrict__ W1)
{
    extern __shared__ float sm[];
    float* sh_comb = sm + OFF_COMB;
    const int b = blockIdx.x;
    const int tid = threadIdx.x;

    float h0f[HH], h1f[HH];
    bool is0; int rp;
    block_matvec(history, cand, W1, b, sm, h0f, h1f, is0, rp);

    // write final h rows into comb for strided stat sums
    if (is0) {
        #pragma unroll
        for (int j = 0; j < HH; j++) {
            sh_comb[rp * 37 + j]         = h0f[j];
            sh_comb[(rp + 100) * 37 + j] = h1f[j];
        }
    }
    __syncthreads();

    float* sh_stats = sm + OFF_W;  // reuse W region
    if (tid < 252) {
        int g = tid / 36, j = tid - g * 36;
        float s = 0.f, s2 = 0.f;
        #pragma unroll 4
        for (int r = g; r < SS; r += 7) {
            float v = sh_comb[r * 37 + j];
            s += v; s2 += v * v;
        }
        sh_stats[g * 72 + j] = s;
        sh_stats[g * 72 + 36 + j] = s2;
    }
    __syncthreads();
    if (tid < 72) {
        float s = 0.f;
        #pragma unroll
        for (int g = 0; g < 7; g++) s += sh_stats[g * 72 + tid];
        g_part[tid * BB + b] = s;
    }
}

// =====================================================================
// Reductions
// =====================================================================
__global__ void reduce_kernel()
{
    __shared__ float red[256];
    const int j = blockIdx.x;
    const float* p = g_part + j * BB;
    float s = 0.f;
    for (int i = threadIdx.x; i < BB; i += 256) s += p[i];
    red[threadIdx.x] = s;
    __syncthreads();
    for (int st = 128; st > 0; st >>= 1) {
        if (threadIdx.x < st) red[threadIdx.x] += red[threadIdx.x + st];
        __syncthreads();
    }
    if (threadIdx.x == 0) g_tot[j] = red[0];
}

__global__ void scalify_kernel(const float* __restrict__ gamma, const float* __restrict__ beta)
{
    int j = threadIdx.x;
    if (j < HH) {
        const float invn = 1.f / (float)NROWS;
        float mu  = g_tot[j] * invn;
        float var = g_tot[HH + j] * invn - mu * mu;
        float sc  = gamma[j] * rsqrtf(var + 1e-5f);
        g_scale[j] = sc;
        g_shift[j] = beta[j] - mu * sc;
    }
}

// =====================================================================
// Pass 2: recompute h, BN affine + Dice + W2 -> w; pooling from smem tile
// =====================================================================
__global__ __launch_bounds__(256) void pass2_kernel(
    const float* __restrict__ history, const float* __restrict__ cand,
    const float* __restrict__ W1, const float* __restrict__ alpha,
    const float* __restrict__ W2, const float* __restrict__ b2,
    float* __restrict__ out)
{
    extern __shared__ float sm[];
    float* sh_hist = sm;
    float* sh_comb = sm + OFF_COMB;
    float* sh_w    = sm + OFF_RW;
    float* sh_sc   = sm + OFF_MISC;
    float* sh_sf   = sm + OFF_MISC + 36;
    float* sh_w2   = sm + OFF_MISC + 72;
    const int b = blockIdx.x;
    const int tid = threadIdx.x;

    // stage BN/Dice params (threads 228..255; visible after matvec's syncs)
    if (tid >= 228) {
        for (int i = tid - 228; i < 110; i += 28) {
            float v;
            if (i < 36)        v = g_scale[i];
            else if (i < 72)   v = g_shift[i - 36];
            else if (i < 108)  v = W2[i - 72];
            else if (i == 108) v = alpha[0];
            else               v = b2[0];
            sh_sc[i] = v;
        }
    }

    float h0f[HH], h1f[HH];
    bool is0; int rp;
    block_matvec(history, cand, W1, b, sm, h0f, h1f, is0, rp);

    if (is0) {
        const float al  = sh_sc[108];
        const float bb2 = sh_sc[109];
        #pragma unroll
        for (int pass = 0; pass < 2; pass++) {
            float* h = pass ? h1f : h0f;
            float m = 0.f, m2 = 0.f;
            #pragma unroll
            for (int j = 0; j < HH; j++) {
                float v = h[j] * sh_sc[j] + sh_sf[j];
                h[j] = v;
                m += v; m2 += v * v;
            }
            m *= (1.f / (float)HH);
            float var = m2 * (1.f / (float)HH) - m * m;
            float inv = rsqrtf(var + 1e-3f);
            float w = bb2;
            #pragma unroll
            for (int j = 0; j < HH; j++) {
                float t  = (h[j] - m) * inv;
                float ps = 1.f / (1.f + __expf(-t));
                w += h[j] * (al + ps * (1.f - al)) * sh_w2[j];
            }
            sh_w[pass ? rp + 100 : rp] = w;
        }
    }
    __syncthreads();

    // pooling: out[b][d] = sum_s w[s] * hist[s][d], from smem tile
    float* sh_pool = sh_comb;  // reuse
    const int sg = tid >> 6;
    const int d  = tid & 63;
    float acc = 0.f;
    #pragma unroll 4
    for (int s = sg; s < SS; s += 4) acc += sh_w[s] * sh_hist[s * 65 + d];
    sh_pool[tid] = acc;
    __syncthreads();
    if (tid < 64)
        out[b * DD + tid] = sh_pool[tid] + sh_pool[tid + 64] + sh_pool[tid + 128] + sh_pool[tid + 192];
}

extern "C" void kernel_launch(void* const* d_in, const int* in_sizes, int n_in,
                              void* d_out, int out_size)
{
    const float* history = (const float*)d_in[0];
    const float* cand    = (const float*)d_in[1];
    const float* W1      = (const float*)d_in[2];
    const float* b1      = (const float*)d_in[3];
    const float* gamma   = (const float*)d_in[4];
    const float* beta    = (const float*)d_in[5];
    const float* alpha   = (const float*)d_in[6];
    const float* W2      = (const float*)d_in[7];
    const float* b2      = (const float*)d_in[8];
    float* out = (float*)d_out;

    const int smem1 = SMEM1_FLOATS * sizeof(float);  // 90,960 B
    const int smem2 = SMEM2_FLOATS * sizeof(float);  // 92,200 B
    cudaFuncSetAttribute(pass1_kernel, cudaFuncAttributeMaxDynamicSharedMemorySize, smem1);
    cudaFuncSetAttribute(pass2_kernel, cudaFuncAttributeMaxDynamicSharedMemorySize, smem2);

    prep_kernel<<<BB / 4, 256>>>(cand, W1, b1);
    pass1_kernel<<<BB, 256, smem1>>>(history, cand, W1);
    reduce_kernel<<<72, 256>>>();
    scalify_kernel<<<1, 64>>>(gamma, beta);
    pass2_kernel<<<BB, 256, smem2>>>(history, cand, W1, alpha, W2, b2, out);
}

// round 4
// speedup vs baseline: 1.6137x; 1.6137x over previous
#include <cuda_runtime.h>
#include <cuda_bf16.h>

#define BB 4096
#define SS 200
#define DD 64
#define HH 36
#define NROWS (BB * SS)

typedef unsigned long long ull;

// Scratch (__device__ globals: allocation-free rule)
__device__ float g_cterm[BB * HH];              // 589 KB
__device__ float g_h[(size_t)NROWS * HH];       // 118 MB pre-BN activations
__device__ float g_w[NROWS];                    // 3.3 MB row weights
__device__ float g_part[72 * BB];               // stat partials [72][B]
__device__ float g_scale[HH];
__device__ float g_shift[HH];

// ---- packed f32x2 helpers (Blackwell FFMA2 via PTX) ----
__device__ __forceinline__ ull pack2(float a) {
    ull r;
    asm("mov.b64 %0, {%1, %1};" : "=l"(r) : "f"(a));
    return r;
}
__device__ __forceinline__ void fma2(ull& d, ull a, ull b) {
    asm("fma.rn.f32x2 %0, %1, %2, %3;" : "=l"(d) : "l"(a), "l"(b), "l"(d));
}
__device__ __forceinline__ float2 unpack2(ull v) {
    float2 f;
    asm("mov.b64 {%0, %1}, %2;" : "=f"(f.x), "=f"(f.y) : "l"(v));
    return f;
}

// pass1 smem (floats): sh_hist [0,13000) stride-65; sh_W [13000,15304); sh_c [15304,15340)
// comb (200x37) aliases sh_hist after compute; stats partials alias sh_W region.
#define OFF_W 13000
#define OFF_C 15304
#define SMEM1_FLOATS 15340

// =====================================================================
// prep: c_term[b][j] = b1[j] + sum_k cand[b][k]*(W1[k][j]+W1[128+k][j])
// =====================================================================
__global__ __launch_bounds__(256) void prep_kernel(
    const float* __restrict__ cand, const float* __restrict__ W1,
    const float* __restrict__ b1)
{
    __shared__ float sW[DD * HH];
    __shared__ float sc[4 * DD];
    const int tid = threadIdx.x;
    const int b0 = blockIdx.x * 4;
    for (int i = tid; i < DD * HH; i += 256) sW[i] = W1[i] + W1[128 * HH + i];
    for (int i = tid; i < 4 * DD; i += 256) sc[i] = cand[b0 * DD + i];
    __syncthreads();
    if (tid < 4 * HH) {
        int bl = tid / HH, j = tid - bl * HH;
        float s = b1[j];
        #pragma unroll 8
        for (int k = 0; k < DD; k++) s += sc[bl * DD + k] * sW[k * HH + j];
        g_cterm[(b0 + bl) * HH + j] = s;
    }
}

// =====================================================================
// Pass 1: h = c_term + hist @ W_eff  (R=2 rows/thread, split-K2),
//         store h to g_h, emit per-block stat partials.
// =====================================================================
__global__ __launch_bounds__(256) void pass1_kernel(
    const float* __restrict__ history, const float* __restrict__ cand,
    const float* __restrict__ W1)
{
    extern __shared__ float sm[];
    float* sh_hist = sm;
    float* sh_W    = sm + OFF_W;
    float* sh_c    = sm + OFF_C;
    const int b = blockIdx.x;
    const int tid = threadIdx.x;

    if (tid < HH) sh_c[tid] = g_cterm[b * HH + tid];
    // W_eff[k][j] = W1[64+k][j] - W1[128+k][j] + cand[k]*W1[192+k][j]
    {
        const float* cb = cand + b * DD;
        #pragma unroll
        for (int i = tid; i < DD * HH; i += 256) {
            int k = i / HH;
            sh_W[i] = W1[64 * HH + i] - W1[128 * HH + i] + __ldg(cb + k) * W1[192 * HH + i];
        }
    }
    // history tile [s][65] (odd stride: conflict-free scalar reads)
    {
        const float4* h4 = (const float4*)(history + (size_t)b * SS * DD);
        #pragma unroll 4
        for (int i4 = tid; i4 < SS * DD / 4; i4 += 256) {
            int s = i4 >> 4, kq = i4 & 15;
            float4 v = h4[i4];
            float* p = sh_hist + s * 65 + kq * 4;
            p[0] = v.x; p[1] = v.y; p[2] = v.z; p[3] = v.w;
        }
    }
    __syncthreads();

    const bool is0 = tid < 100;
    const bool is1 = (tid >= 128 && tid < 228);
    const int rp = is0 ? tid : tid - 128;

    ull acc0[18], acc1[18];
    if (is0) {
        const ull* c2 = (const ull*)sh_c;
        #pragma unroll
        for (int q = 0; q < 18; q++) { acc0[q] = c2[q]; acc1[q] = c2[q]; }
    } else {
        #pragma unroll
        for (int q = 0; q < 18; q++) { acc0[q] = 0ull; acc1[q] = 0ull; }
    }

    if (is0 | is1) {
        const int k0 = is0 ? 0 : 32;
        const float* r0 = sh_hist + rp * 65 + k0;
        const float* r1 = sh_hist + (rp + 100) * 65 + k0;
        const char* Wb = (const char*)(sh_W + k0 * HH);
        #pragma unroll 4
        for (int kk = 0; kk < 32; kk++) {
            ull H0 = pack2(r0[kk]);
            ull H1 = pack2(r1[kk]);
            const ulonglong2* Wk = (const ulonglong2*)(Wb + kk * (HH * 4));
            #pragma unroll
            for (int q = 0; q < 9; q++) {
                ulonglong2 w = Wk[q];
                fma2(acc0[2 * q],     H0, w.x);
                fma2(acc0[2 * q + 1], H0, w.y);
                fma2(acc1[2 * q],     H1, w.x);
                fma2(acc1[2 * q + 1], H1, w.y);
            }
        }
    }
    __syncthreads();   // all sh_hist reads done; safe to alias comb onto it

    float* comb = sm;  // 200 x 37
    if (is1) {
        #pragma unroll
        for (int q = 0; q < 18; q++) {
            float2 f0 = unpack2(acc0[q]);
            float2 f1 = unpack2(acc1[q]);
            comb[rp * 37 + 2 * q]             = f0.x;
            comb[rp * 37 + 2 * q + 1]         = f0.y;
            comb[(rp + 100) * 37 + 2 * q]     = f1.x;
            comb[(rp + 100) * 37 + 2 * q + 1] = f1.y;
        }
    }
    __syncthreads();
    if (is0) {
        #pragma unroll
        for (int q = 0; q < 18; q++) {
            float2 f0 = unpack2(acc0[q]);
            float2 f1 = unpack2(acc1[q]);
            comb[rp * 37 + 2 * q]             += f0.x;
            comb[rp * 37 + 2 * q + 1]         += f0.y;
            comb[(rp + 100) * 37 + 2 * q]     += f1.x;
            comb[(rp + 100) * 37 + 2 * q + 1] += f1.y;
        }
    }
    __syncthreads();

    // coalesced h store: gh[i] = comb[i + i/36]  (i = s*36+j -> s*37+j)
    {
        float* gh = g_h + (size_t)b * SS * HH;
        #pragma unroll 4
        for (int i = tid; i < SS * HH; i += 256)
            gh[i] = comb[i + i / 36];
    }
    // per-feature partial sums: 7 row-groups x 36 features
    float* st = sm + OFF_W;  // reuse W region (W reads finished)
    if (tid < 252) {
        int g = tid / 36, j = tid - g * 36;
        float s = 0.f, s2 = 0.f;
        #pragma unroll 4
        for (int r = g; r < SS; r += 7) {
            float v = comb[r * 37 + j];
            s += v; s2 += v * v;
        }
        st[g * 72 + j] = s;
        st[g * 72 + 36 + j] = s2;
    }
    __syncthreads();
    if (tid < 72) {
        float s = 0.f;
        #pragma unroll
        for (int g = 0; g < 7; g++) s += st[g * 72 + tid];
        g_part[tid * BB + b] = s;
    }
}

// =====================================================================
// Fused reduce + BN scale/shift: 36 blocks, each handles sum & sumsq of one j
// =====================================================================
__global__ __launch_bounds__(256) void reduce_kernel(
    const float* __restrict__ gamma, const float* __restrict__ beta)
{
    __shared__ float r1[256], r2[256];
    const int j = blockIdx.x;
    const int tid = threadIdx.x;
    float s = 0.f, s2 = 0.f;
    const float* p1 = g_part + j * BB;
    const float* p2 = g_part + (HH + j) * BB;
    for (int i = tid; i < BB; i += 256) { s += p1[i]; s2 += p2[i]; }
    r1[tid] = s; r2[tid] = s2;
    __syncthreads();
    for (int st = 128; st > 0; st >>= 1) {
        if (tid < st) { r1[tid] += r1[tid + st]; r2[tid] += r2[tid + st]; }
        __syncthreads();
    }
    if (tid == 0) {
        const float invn = 1.f / (float)NROWS;
        float mu  = r1[0] * invn;
        float var = r2[0] * invn - mu * mu;
        float sc  = gamma[j] * rsqrtf(var + 1e-5f);
        g_scale[j] = sc;
        g_shift[j] = beta[j] - mu * sc;
    }
}

// =====================================================================
// wcomp: row-per-thread. read h row, BN affine + Dice + W2 -> g_w[row]
// =====================================================================
__global__ __launch_bounds__(256) void wcomp_kernel(
    const float* __restrict__ alpha, const float* __restrict__ W2,
    const float* __restrict__ b2)
{
    __shared__ float par[112];
    const int tid = threadIdx.x;
    if (tid < 110) {
        float v;
        if (tid < 36)        v = g_scale[tid];
        else if (tid < 72)   v = g_shift[tid - 36];
        else if (tid < 108)  v = W2[tid - 72];
        else if (tid == 108) v = alpha[0];
        else                 v = b2[0];
        par[tid] = v;
    }
    __syncthreads();

    const int row = blockIdx.x * 256 + tid;   // grid = 3200 -> exactly NROWS
    const float4* hr = (const float4*)(g_h + (size_t)row * HH);
    float h[HH];
    #pragma unroll
    for (int q = 0; q < 9; q++) {
        float4 v = hr[q];
        h[4 * q] = v.x; h[4 * q + 1] = v.y; h[4 * q + 2] = v.z; h[4 * q + 3] = v.w;
    }
    float m = 0.f, m2 = 0.f;
    #pragma unroll
    for (int j = 0; j < HH; j++) {
        float v = h[j] * par[j] + par[36 + j];
        h[j] = v;
        m += v; m2 += v * v;
    }
    m *= (1.f / (float)HH);
    float var = m2 * (1.f / (float)HH) - m * m;
    float inv = rsqrtf(var + 1e-3f);
    const float al = par[108];
    float w = par[109];
    #pragma unroll
    for (int j = 0; j < HH; j++) {
        float t  = (h[j] - m) * inv;
        float ps = 1.f / (1.f + __expf(-t));
        w += h[j] * (al + ps * (1.f - al)) * par[72 + j];
    }
    g_w[row] = w;
}

// =====================================================================
// pool: out[b][d] = sum_s g_w[b][s] * hist[b][s][d]
// =====================================================================
__global__ __launch_bounds__(256) void pool_kernel(
    const float* __restrict__ history, float* __restrict__ out)
{
    __shared__ float sw[SS];
    __shared__ float pool[256];
    const int b = blockIdx.x;
    const int tid = threadIdx.x;
    if (tid < SS) sw[tid] = g_w[b * SS + tid];
    __syncthreads();
    const float* hb = history + (size_t)b * SS * DD;
    const int sg = tid >> 6;
    const int d  = tid & 63;
    float acc = 0.f;
    #pragma unroll 5
    for (int s = sg; s < SS; s += 4) acc += sw[s] * hb[s * DD + d];
    pool[tid] = acc;
    __syncthreads();
    if (tid < 64)
        out[b * DD + tid] = pool[tid] + pool[tid + 64] + pool[tid + 128] + pool[tid + 192];
}

extern "C" void kernel_launch(void* const* d_in, const int* in_sizes, int n_in,
                              void* d_out, int out_size)
{
    const float* history = (const float*)d_in[0];
    const float* cand    = (const float*)d_in[1];
    const float* W1      = (const float*)d_in[2];
    const float* b1      = (const float*)d_in[3];
    const float* gamma   = (const float*)d_in[4];
    const float* beta    = (const float*)d_in[5];
    const float* alpha   = (const float*)d_in[6];
    const float* W2      = (const float*)d_in[7];
    const float* b2      = (const float*)d_in[8];
    float* out = (float*)d_out;

    const int smem1 = SMEM1_FLOATS * sizeof(float);  // 61,360 B
    cudaFuncSetAttribute(pass1_kernel, cudaFuncAttributeMaxDynamicSharedMemorySize, smem1);

    prep_kernel<<<BB / 4, 256>>>(cand, W1, b1);
    pass1_kernel<<<BB, 256, smem1>>>(history, cand, W1);
    reduce_kernel<<<HH, 256>>>(gamma, beta);
    wcomp_kernel<<<NROWS / 256, 256>>>(alpha, W2, b2);
    pool_kernel<<<BB, 256>>>(history, out);
}

// round 5
// speedup vs baseline: 1.7263x; 1.0698x over previous
#include <cuda_runtime.h>
#include <cuda_bf16.h>

#define BB 4096
#define SS 200
#define DD 64
#define HH 36
#define NROWS (BB * SS)

typedef unsigned long long ull;

// Scratch (__device__ globals: allocation-free rule)
__device__ float g_cterm[BB * HH];              // 589 KB
__device__ float g_h[(size_t)NROWS * HH];       // 118 MB pre-BN activations
__device__ float g_part[72 * BB];               // stat partials [72][B]
__device__ float g_scale[HH];
__device__ float g_shift[HH];

// ---- packed f32x2 helpers (Blackwell FFMA2 via PTX) ----
__device__ __forceinline__ ull pack2(float a) {
    ull r;
    asm("mov.b64 %0, {%1, %1};" : "=l"(r) : "f"(a));
    return r;
}
__device__ __forceinline__ void fma2(ull& d, ull a, ull b) {
    asm("fma.rn.f32x2 %0, %1, %2, %3;" : "=l"(d) : "l"(a), "l"(b), "l"(d));
}
__device__ __forceinline__ float2 unpack2(ull v) {
    float2 f;
    asm("mov.b64 {%0, %1}, %2;" : "=f"(f.x), "=f"(f.y) : "l"(v));
    return f;
}

// pass1 smem (floats): sh_hist [0,13000) stride-65; sh_W [13000,15304); sh_c [15304,15340)
// comb (200x36, contiguous) aliases sh_hist after compute; stats alias sh_W region.
#define OFF_W 13000
#define OFF_C 15304
#define SMEM1_FLOATS 15340

// =====================================================================
// prep: c_term[b][j] = b1[j] + sum_k cand[b][k]*(W1[k][j]+W1[128+k][j])
// =====================================================================
__global__ __launch_bounds__(256) void prep_kernel(
    const float* __restrict__ cand, const float* __restrict__ W1,
    const float* __restrict__ b1)
{
    __shared__ float sW[DD * HH];
    __shared__ float sc[4 * DD];
    const int tid = threadIdx.x;
    const int b0 = blockIdx.x * 4;
    for (int i = tid; i < DD * HH; i += 256) sW[i] = W1[i] + W1[128 * HH + i];
    for (int i = tid; i < 4 * DD; i += 256) sc[i] = cand[b0 * DD + i];
    __syncthreads();
    if (tid < 4 * HH) {
        int bl = tid / HH, j = tid - bl * HH;
        float s = b1[j];
        #pragma unroll 8
        for (int k = 0; k < DD; k++) s += sc[bl * DD + k] * sW[k * HH + j];
        g_cterm[(b0 + bl) * HH + j] = s;
    }
}

// =====================================================================
// Pass 1: h = c_term + hist @ W_eff  (R=2 rows/thread, split-K2),
//         store h to g_h (float4), emit per-block stat partials.
// =====================================================================
__global__ __launch_bounds__(256) void pass1_kernel(
    const float* __restrict__ history, const float* __restrict__ cand,
    const float* __restrict__ W1)
{
    extern __shared__ float sm[];
    float* sh_hist = sm;
    float* sh_W    = sm + OFF_W;
    float* sh_c    = sm + OFF_C;
    const int b = blockIdx.x;
    const int tid = threadIdx.x;

    if (tid < HH) sh_c[tid] = g_cterm[b * HH + tid];
    // W_eff[k][j] = W1[64+k][j] - W1[128+k][j] + cand[k]*W1[192+k][j]
    {
        const float* cb = cand + b * DD;
        #pragma unroll
        for (int i = tid; i < DD * HH; i += 256) {
            int k = i / HH;
            sh_W[i] = W1[64 * HH + i] - W1[128 * HH + i] + __ldg(cb + k) * W1[192 * HH + i];
        }
    }
    // history tile [s][65] (odd stride: conflict-free scalar reads)
    {
        const float4* h4 = (const float4*)(history + (size_t)b * SS * DD);
        #pragma unroll
        for (int i4 = tid; i4 < SS * DD / 4; i4 += 256) {
            int s = i4 >> 4, kq = i4 & 15;
            float4 v = h4[i4];
            float* p = sh_hist + s * 65 + kq * 4;
            p[0] = v.x; p[1] = v.y; p[2] = v.z; p[3] = v.w;
        }
    }
    __syncthreads();

    const bool is0 = tid < 100;
    const bool is1 = (tid >= 128 && tid < 228);
    const int rp = is0 ? tid : tid - 128;

    ull acc0[18], acc1[18];
    if (is0) {
        const ull* c2 = (const ull*)sh_c;
        #pragma unroll
        for (int q = 0; q < 18; q++) { acc0[q] = c2[q]; acc1[q] = c2[q]; }
    } else {
        #pragma unroll
        for (int q = 0; q < 18; q++) { acc0[q] = 0ull; acc1[q] = 0ull; }
    }

    if (is0 | is1) {
        const int k0 = is0 ? 0 : 32;
        const float* r0 = sh_hist + rp * 65 + k0;
        const float* r1 = sh_hist + (rp + 100) * 65 + k0;
        const char* Wb = (const char*)(sh_W + k0 * HH);
        #pragma unroll 4
        for (int kk = 0; kk < 32; kk++) {
            ull H0 = pack2(r0[kk]);
            ull H1 = pack2(r1[kk]);
            const ulonglong2* Wk = (const ulonglong2*)(Wb + kk * (HH * 4));
            #pragma unroll
            for (int q = 0; q < 9; q++) {
                ulonglong2 w = Wk[q];
                fma2(acc0[2 * q],     H0, w.x);
                fma2(acc0[2 * q + 1], H0, w.y);
                fma2(acc1[2 * q],     H1, w.x);
                fma2(acc1[2 * q + 1], H1, w.y);
            }
        }
    }
    __syncthreads();   // all sh_hist reads done; safe to alias comb onto it

    float* comb = sm;  // 200 x 36, contiguous (7200 floats)
    if (is1) {
        ull* c0 = (ull*)(comb + rp * HH);
        ull* c1 = (ull*)(comb + (rp + 100) * HH);
        #pragma unroll
        for (int q = 0; q < 18; q++) { c0[q] = acc0[q]; c1[q] = acc1[q]; }
    }
    __syncthreads();
    if (is0) {
        ull* c0 = (ull*)(comb + rp * HH);
        ull* c1 = (ull*)(comb + (rp + 100) * HH);
        #pragma unroll
        for (int q = 0; q < 18; q++) {
            float2 p0 = unpack2(c0[q]);
            float2 p1 = unpack2(c1[q]);
            float2 f0 = unpack2(acc0[q]);
            float2 f1 = unpack2(acc1[q]);
            f0.x += p0.x; f0.y += p0.y;
            f1.x += p1.x; f1.y += p1.y;
            ull o0, o1;
            asm("mov.b64 %0, {%1, %2};" : "=l"(o0) : "f"(f0.x), "f"(f0.y));
            asm("mov.b64 %0, {%1, %2};" : "=l"(o1) : "f"(f1.x), "f"(f1.y));
            c0[q] = o0;
            c1[q] = o1;
        }
    }
    __syncthreads();

    // coalesced vector store of h: 1800 float4
    {
        float4* gh4 = (float4*)(g_h + (size_t)b * SS * HH);
        const float4* c4 = (const float4*)comb;
        #pragma unroll
        for (int i4 = tid; i4 < SS * HH / 4; i4 += 256)
            gh4[i4] = c4[i4];
    }
    // per-feature partial sums: 7 row-groups x 36 features
    float* st = sm + OFF_W;  // reuse W region (W reads finished)
    if (tid < 252) {
        int g = tid / 36, j = tid - g * 36;
        float s = 0.f, s2 = 0.f;
        #pragma unroll 4
        for (int r = g; r < SS; r += 7) {
            float v = comb[r * HH + j];
            s += v; s2 += v * v;
        }
        st[g * 72 + j] = s;
        st[g * 72 + 36 + j] = s2;
    }
    __syncthreads();
    if (tid < 72) {
        float s = 0.f;
        #pragma unroll
        for (int g = 0; g < 7; g++) s += st[g * 72 + tid];
        g_part[tid * BB + b] = s;
    }
}

// =====================================================================
// Fused reduce + BN scale/shift: 36 blocks, each handles sum & sumsq of one j
// =====================================================================
__global__ __launch_bounds__(256) void reduce_kernel(
    const float* __restrict__ gamma, const float* __restrict__ beta)
{
    __shared__ float r1[256], r2[256];
    const int j = blockIdx.x;
    const int tid = threadIdx.x;
    float s = 0.f, s2 = 0.f;
    const float* p1 = g_part + j * BB;
    const float* p2 = g_part + (HH + j) * BB;
    for (int i = tid; i < BB; i += 256) { s += p1[i]; s2 += p2[i]; }
    r1[tid] = s; r2[tid] = s2;
    __syncthreads();
    for (int st = 128; st > 0; st >>= 1) {
        if (tid < st) { r1[tid] += r1[tid + st]; r2[tid] += r2[tid + st]; }
        __syncthreads();
    }
    if (tid == 0) {
        const float invn = 1.f / (float)NROWS;
        float mu  = r1[0] * invn;
        float var = r2[0] * invn - mu * mu;
        float sc  = gamma[j] * rsqrtf(var + 1e-5f);
        g_scale[j] = sc;
        g_shift[j] = beta[j] - mu * sc;
    }
}

// =====================================================================
// finish: per batch. stage h slice, BN+Dice+W2 -> w (row/thread),
//         then weighted pooling over streamed history.
// =====================================================================
__global__ __launch_bounds__(256) void finish_kernel(
    const float* __restrict__ history, const float* __restrict__ alpha,
    const float* __restrict__ W2, const float* __restrict__ b2,
    float* __restrict__ out)
{
    __shared__ float sh[SS * HH];     // 7200 floats, contiguous
    __shared__ float sw[SS];
    __shared__ float pool[256];
    __shared__ float par[112];
    const int b = blockIdx.x;
    const int tid = threadIdx.x;

    if (tid < 110) {
        float v;
        if (tid < 36)        v = g_scale[tid];
        else if (tid < 72)   v = g_shift[tid - 36];
        else if (tid < 108)  v = W2[tid - 72];
        else if (tid == 108) v = alpha[0];
        else                 v = b2[0];
        par[tid] = v;
    }
    // stage h slice (coalesced float4)
    {
        const float4* gh4 = (const float4*)(g_h + (size_t)b * SS * HH);
        float4* s4 = (float4*)sh;
        #pragma unroll
        for (int i4 = tid; i4 < SS * HH / 4; i4 += 256)
            s4[i4] = gh4[i4];
    }
    __syncthreads();

    if (tid < SS) {
        const float* hr = sh + tid * HH;
        float h[HH];
        float m = 0.f, m2 = 0.f;
        #pragma unroll
        for (int j = 0; j < HH; j++) {
            float v = hr[j] * par[j] + par[36 + j];
            h[j] = v;
            m += v; m2 += v * v;
        }
        m *= (1.f / (float)HH);
        float var = m2 * (1.f / (float)HH) - m * m;
        float inv = rsqrtf(var + 1e-3f);
        const float al = par[108];
        float w = par[109];
        #pragma unroll
        for (int j = 0; j < HH; j++) {
            float t  = (h[j] - m) * inv;
            float ps = 1.f / (1.f + __expf(-t));
            w += h[j] * (al + ps * (1.f - al)) * par[72 + j];
        }
        sw[tid] = w;
    }
    __syncthreads();

    // pooling: out[b][d] = sum_s sw[s] * hist[b][s][d]
    const float* hb = history + (size_t)b * SS * DD;
    const int sg = tid >> 6;
    const int d  = tid & 63;
    float acc = 0.f;
    #pragma unroll 10
    for (int s = sg; s < SS; s += 4) acc += sw[s] * hb[s * DD + d];
    pool[tid] = acc;
    __syncthreads();
    if (tid < 64)
        out[b * DD + tid] = pool[tid] + pool[tid + 64] + pool[tid + 128] + pool[tid + 192];
}

extern "C" void kernel_launch(void* const* d_in, const int* in_sizes, int n_in,
                              void* d_out, int out_size)
{
    const float* history = (const float*)d_in[0];
    const float* cand    = (const float*)d_in[1];
    const float* W1      = (const float*)d_in[2];
    const float* b1      = (const float*)d_in[3];
    const float* gamma   = (const float*)d_in[4];
    const float* beta    = (const float*)d_in[5];
    const float* alpha   = (const float*)d_in[6];
    const float* W2      = (const float*)d_in[7];
    const float* b2      = (const float*)d_in[8];
    float* out = (float*)d_out;

    const int smem1 = SMEM1_FLOATS * sizeof(float);  // 61,360 B
    cudaFuncSetAttribute(pass1_kernel, cudaFuncAttributeMaxDynamicSharedMemorySize, smem1);

    prep_kernel<<<BB / 4, 256>>>(cand, W1, b1);
    pass1_kernel<<<BB, 256, smem1>>>(history, cand, W1);
    reduce_kernel<<<HH, 256>>>(gamma, beta);
    finish_kernel<<<BB, 256>>>(history, alpha, W2, b2, out);
}